// round 8
// baseline (speedup 1.0000x reference)
#include <cuda_runtime.h>
#include <math.h>
#include <stdint.h>

#define T_DIM 2048
#define H_DIM 2048
#define I_DIM 2880
#define E_DIM 8
#define GU_DIM 5760

// ---------------- scratch ----------------
__device__ __align__(1024) float g_rx  [(size_t)T_DIM * H_DIM];
__device__ __align__(1024) float g_wsgu[(size_t)GU_DIM * H_DIM];
__device__ __align__(1024) float g_rsd [(size_t)H_DIM * I_DIM];
__device__ __align__(1024) float g_gus [(size_t)T_DIM * GU_DIM];
__device__ __align__(1024) float g_acts[(size_t)T_DIM * I_DIM];
__device__ __align__(1024) float g_gur [(size_t)2 * T_DIM * GU_DIM];
__device__ __align__(1024) float g_actr[(size_t)2 * T_DIM * I_DIM];
__device__ int   g_cnt[E_DIM];
__device__ int   g_ptok[E_DIM * T_DIM];
__device__ int   g_pgp [E_DIM * T_DIM];
__device__ float g_pscl[E_DIM * T_DIM];

// ---------------- helpers ----------------
__device__ __forceinline__ uint32_t f2tf(float f) {
    uint32_t u;
    asm("cvt.rna.tf32.f32 %0, %1;" : "=r"(u) : "f"(f));
    return u;
}
__device__ __forceinline__ float rtf(float f) { return __uint_as_float(f2tf(f)); }
__device__ __forceinline__ void cpasync16(uint32_t dst, const void* src) {
    asm volatile("cp.async.cg.shared.global [%0], [%1], 16;" :: "r"(dst), "l"(src));
}
__device__ __forceinline__ float silu_mul(float g, float u) {
    return u * g / (1.f + expf(-g));
}

// ---------------- prepass kernels ----------------
// round + k-permute copy: within each group of 8, stored[2j]=log[j], stored[2j+1]=log[j+4]
__global__ void round_perm_copy(const float4* __restrict__ src,
                                float4* __restrict__ dst, long n8) {
    long stride = (long)gridDim.x * blockDim.x;
    for (long g = (long)blockIdx.x * blockDim.x + threadIdx.x; g < n8; g += stride) {
        float4 a = src[g * 2], b = src[g * 2 + 1];
        float4 o0, o1;
        o0.x = rtf(a.x); o0.y = rtf(b.x); o0.z = rtf(a.y); o0.w = rtf(b.y);
        o1.x = rtf(a.z); o1.y = rtf(b.z); o1.z = rtf(a.w); o1.w = rtf(b.w);
        dst[g * 2]     = o0;
        dst[g * 2 + 1] = o1;
    }
}

// act[r][perm(i)] = round(silu(gu[r][i]) * gu[r][I+i])
__global__ void act_perm_kernel(const float* __restrict__ gu,
                                float* __restrict__ dst, int rows) {
    long total = (long)rows * (I_DIM / 8);
    long stride = (long)gridDim.x * blockDim.x;
    for (long idx = (long)blockIdx.x * blockDim.x + threadIdx.x; idx < total; idx += stride) {
        long r = idx / (I_DIM / 8);
        int c = (int)(idx % (I_DIM / 8)) * 8;
        const float* row = gu + r * GU_DIM;
        float4 ga = *(const float4*)(row + c);
        float4 gb = *(const float4*)(row + c + 4);
        float4 ua = *(const float4*)(row + I_DIM + c);
        float4 ub = *(const float4*)(row + I_DIM + c + 4);
        float v0 = rtf(silu_mul(ga.x, ua.x));
        float v1 = rtf(silu_mul(ga.y, ua.y));
        float v2 = rtf(silu_mul(ga.z, ua.z));
        float v3 = rtf(silu_mul(ga.w, ua.w));
        float v4 = rtf(silu_mul(gb.x, ub.x));
        float v5 = rtf(silu_mul(gb.y, ub.y));
        float v6 = rtf(silu_mul(gb.z, ub.z));
        float v7 = rtf(silu_mul(gb.w, ub.w));
        float4 o0, o1;
        o0.x = v0; o0.y = v4; o0.z = v1; o0.w = v5;
        o1.x = v2; o1.y = v6; o1.z = v3; o1.w = v7;
        *(float4*)(dst + r * I_DIM + c)     = o0;
        *(float4*)(dst + r * I_DIM + c + 4) = o1;
    }
}

// ---------------- router ----------------
__global__ void zero_cnt_kernel() {
    if (threadIdx.x < E_DIM) g_cnt[threadIdx.x] = 0;
}

__global__ void router_kernel(const float* __restrict__ x,
                              const float* __restrict__ rw,
                              float* __restrict__ out, int writeScores) {
    int t = blockIdx.x * 8 + (threadIdx.x >> 5);
    int lane = threadIdx.x & 31;
    if (t >= T_DIM) return;
    const float* xr = x + (size_t)t * H_DIM;
    float s[E_DIM];
#pragma unroll
    for (int e = 0; e < E_DIM; e++) s[e] = 0.f;
    for (int h = lane; h < H_DIM; h += 32) {
        float xv = xr[h];
#pragma unroll
        for (int e = 0; e < E_DIM; e++) s[e] += xv * rw[e * H_DIM + h];
    }
#pragma unroll
    for (int e = 0; e < E_DIM; e++) {
#pragma unroll
        for (int off = 16; off > 0; off >>= 1)
            s[e] += __shfl_xor_sync(0xffffffffu, s[e], off);
    }
    if (lane == 0) {
        int i1 = 0; float v1 = s[0];
#pragma unroll
        for (int e = 1; e < E_DIM; e++) if (s[e] > v1) { v1 = s[e]; i1 = e; }
        int i2 = -1; float v2 = -INFINITY;
#pragma unroll
        for (int e = 0; e < E_DIM; e++) if (e != i1 && s[e] > v2) { v2 = s[e]; i2 = e; }
        float sg1 = 1.f / (1.f + expf(-v1));
        float sg2 = 1.f / (1.f + expf(-v2));
        if (writeScores) {
            float* rs = out + (size_t)T_DIM * H_DIM;
#pragma unroll
            for (int e = 0; e < E_DIM; e++)
                rs[(size_t)e * T_DIM + t] = (e == i1) ? sg1 : ((e == i2) ? sg2 : 0.f);
        }
        int p1 = atomicAdd(&g_cnt[i1], 1);
        g_ptok[i1 * T_DIM + p1] = t;
        g_pgp [i1 * T_DIM + p1] = t * 2;
        g_pscl[i1 * T_DIM + p1] = sg1;
        int p2 = atomicAdd(&g_cnt[i2], 1);
        g_ptok[i2 * T_DIM + p2] = t;
        g_pgp [i2 * T_DIM + p2] = t * 2 + 1;
        g_pscl[i2 * T_DIM + p2] = sg2;
    }
}

// ---------------- TF32 mma.sync GEMM (single instantiation, runtime modes) ----------------
// bmode 0 (NT): B rows K-major, pre-rounded + k-permuted, row stride ldb.
// bmode 1 (NN): B raw [k][n] layout, row stride ldb; rounded in-loop via cvt.rna.
// mode bits: 1 gather A rows, 2 scatter C rows, 4 scale rows, 8 atomicAdd C.
#define BM 128
#define BN 256
#define BK 32
#define AST 36
#define BNN_ST 264
#define A_TILE_F (BM * AST)      // 4608
#define B_TILE_F (BN * AST)      // 9216 (covers NN's 32*264=8448 too)
#define STAGE_F (A_TILE_F + B_TILE_F)
#define NSTAGE 3
#define DYN_SMEM (NSTAGE * STAGE_F * 4)   // 165888

__global__ void __launch_bounds__(256, 1)
gemm_tf32(const float* __restrict__ A, const float* __restrict__ B,
          float* __restrict__ C,
          int M, int N, int K, int ldb, int ldc, int bmode, int mode,
          const int* __restrict__ idxA, const int* __restrict__ idxC,
          const float* __restrict__ sclA, const int* __restrict__ cntArr,
          size_t bStride)
{
    extern __shared__ float smem[];
    __shared__ int   s_rowA[BM];
    __shared__ int   s_rowC[BM];
    __shared__ float s_scl [BM];

    const int e = blockIdx.z;
    const int mLim = cntArr ? cntArr[e] : M;
    const int m0 = blockIdx.y * BM;
    if (m0 >= mLim) return;
    const int n0 = blockIdx.x * BN;
    const int nThis = min(BN, N - n0);
    const int lb = e * T_DIM;
    const float* Bp = B + (size_t)e * bStride;

    const int tid = threadIdx.x, lane = tid & 31, warp = tid >> 5;
    const int wm = (warp & 1) * 64, wn = (warp >> 1) * 64;
    const int gid = lane >> 2, tig = lane & 3;
    const int numK = K / BK;

    uint32_t sbase = (uint32_t)__cvta_generic_to_shared(smem);

    if (mode & 1) {
        for (int i = tid; i < BM; i += 256) {
            int ml = min(m0 + i, mLim - 1);
            s_rowA[i] = idxA[lb + ml];
        }
    }
    if (mode & 2) {
        for (int i = tid; i < BM; i += 256) {
            int ml = min(m0 + i, mLim - 1);
            s_rowC[i] = idxC[lb + ml];
            s_scl[i] = (mode & 4) ? sclA[lb + ml] : 1.f;
        }
    }
    if (mode & 3) __syncthreads();

    float acc[4][8][4];
#pragma unroll
    for (int a = 0; a < 4; a++)
#pragma unroll
        for (int b = 0; b < 8; b++)
#pragma unroll
            for (int c = 0; c < 4; c++) acc[a][b][c] = 0.f;

    auto issue_loads = [&](int kt) {
        int st = kt % NSTAGE;
        uint32_t aB = sbase + st * STAGE_F * 4;
        uint32_t bB = aB + A_TILE_F * 4;
        const float* Acol = A + (size_t)kt * BK;
#pragma unroll
        for (int i = 0; i < 4; i++) {
            int cc = tid + i * 256;
            int r = cc >> 3, kc = cc & 7;
            int gm = (mode & 1) ? s_rowA[r] : m0 + r;
            cpasync16(aB + (r * AST + kc * 4) * 4,
                      Acol + (size_t)gm * K + kc * 4);
        }
        if (bmode == 0) {
            const float* Bcol = Bp + (size_t)kt * BK;
#pragma unroll
            for (int i = 0; i < 8; i++) {
                int cc = tid + i * 256;
                int r = cc >> 3, kc = cc & 7;
                if (r < nThis)
                    cpasync16(bB + (r * AST + kc * 4) * 4,
                              Bcol + (size_t)(n0 + r) * ldb + kc * 4);
            }
        } else {
            const float* Brow = Bp + (size_t)kt * BK * ldb + n0;
            float* BsW = smem + st * STAGE_F + A_TILE_F;
#pragma unroll
            for (int i = 0; i < 8; i++) {
                int cc = tid + i * 256;
                int r = cc >> 6, c4 = cc & 63;  // 32 rows x 64 float4-chunks
                if (n0 + c4 * 4 < N) {
                    cpasync16(bB + (r * BNN_ST + c4 * 4) * 4,
                              Brow + (size_t)r * ldb + c4 * 4);
                } else {
                    *(float4*)&BsW[r * BNN_ST + c4 * 4] =
                        make_float4(0.f, 0.f, 0.f, 0.f);
                }
            }
        }
        asm volatile("cp.async.commit_group;");
    };

#pragma unroll
    for (int kt = 0; kt < NSTAGE; kt++) issue_loads(kt);

    for (int kt = 0; kt < numK; kt++) {
        int st = kt % NSTAGE;
        asm volatile("cp.async.wait_group %0;" :: "n"(NSTAGE - 1));
        __syncthreads();
        const float* As = smem + st * STAGE_F;
        const float* Bs = As + A_TILE_F;
#pragma unroll
        for (int ks = 0; ks < 4; ks++) {
            const int kc = ks * 8 + 2 * tig;  // permuted (tig, tig+4) pair for A
            uint32_t af[4][4];
#pragma unroll
            for (int mt = 0; mt < 4; mt++) {
                float2 v0 = *(const float2*)&As[(wm + mt * 16 + gid) * AST + kc];
                float2 v1 = *(const float2*)&As[(wm + mt * 16 + 8 + gid) * AST + kc];
                af[mt][0] = __float_as_uint(v0.x);
                af[mt][1] = __float_as_uint(v1.x);
                af[mt][2] = __float_as_uint(v0.y);
                af[mt][3] = __float_as_uint(v1.y);
            }
            uint32_t bf[8][2];
            if (bmode == 0) {
#pragma unroll
                for (int nt = 0; nt < 8; nt++) {
                    float2 b = *(const float2*)&Bs[(wn + nt * 8 + gid) * AST + kc];
                    bf[nt][0] = __float_as_uint(b.x);
                    bf[nt][1] = __float_as_uint(b.y);
                }
            } else {
                const int k0 = ks * 8;
#pragma unroll
                for (int nt = 0; nt < 8; nt++) {
                    int col = wn + nt * 8 + gid;
                    bf[nt][0] = f2tf(Bs[(k0 + tig) * BNN_ST + col]);
                    bf[nt][1] = f2tf(Bs[(k0 + tig + 4) * BNN_ST + col]);
                }
            }
#pragma unroll
            for (int mt = 0; mt < 4; mt++)
#pragma unroll
                for (int nt = 0; nt < 8; nt++) {
                    asm volatile(
                        "mma.sync.aligned.m16n8k8.row.col.f32.tf32.tf32.f32 "
                        "{%0,%1,%2,%3}, {%4,%5,%6,%7}, {%8,%9}, {%0,%1,%2,%3};"
                        : "+f"(acc[mt][nt][0]), "+f"(acc[mt][nt][1]),
                          "+f"(acc[mt][nt][2]), "+f"(acc[mt][nt][3])
                        : "r"(af[mt][0]), "r"(af[mt][1]), "r"(af[mt][2]), "r"(af[mt][3]),
                          "r"(bf[nt][0]), "r"(bf[nt][1]));
                }
        }
        __syncthreads();
        if (kt + NSTAGE < numK) issue_loads(kt + NSTAGE);
        else asm volatile("cp.async.commit_group;");
    }

#pragma unroll
    for (int mt = 0; mt < 4; mt++) {
#pragma unroll
        for (int rr = 0; rr < 2; rr++) {
            int ml  = wm + mt * 16 + gid + rr * 8;
            int gml = m0 + ml;
            if (gml >= mLim) continue;
            float* crow;
            float sc = 1.f;
            if (mode & 2) {
                crow = C + (size_t)s_rowC[ml] * ldc;
                sc = s_scl[ml];
            } else {
                crow = C + (size_t)gml * ldc;
            }
#pragma unroll
            for (int nt = 0; nt < 8; nt++) {
                int cn = n0 + wn + nt * 8 + tig * 2;
                if (cn >= n0 + nThis) continue;
                float v0 = acc[mt][nt][rr * 2 + 0] * sc;
                float v1 = acc[mt][nt][rr * 2 + 1] * sc;
                if (mode & 8) {
                    atomicAdd(crow + cn, v0);
                    atomicAdd(crow + cn + 1, v1);
                } else {
                    *(float2*)(crow + cn) = make_float2(v0, v1);
                }
            }
        }
    }
}

// ---------------- launch ----------------
extern "C" void kernel_launch(void* const* d_in, const int* in_sizes, int n_in,
                              void* d_out, int out_size) {
    const float* x   = (const float*)d_in[0];
    const float* rw  = (const float*)d_in[1];
    const float* gup = (const float*)d_in[2];
    const float* dwn = (const float*)d_in[3];
    const float* sg  = (const float*)d_in[4];
    const float* su  = (const float*)d_in[5];
    const float* sd  = (const float*)d_in[6];
    float* out = (float*)d_out;

    void* p;
    cudaGetSymbolAddress(&p, g_rx);    float* rx    = (float*)p;
    cudaGetSymbolAddress(&p, g_wsgu);  float* wsgu  = (float*)p;
    cudaGetSymbolAddress(&p, g_rsd);   float* rsd   = (float*)p;
    cudaGetSymbolAddress(&p, g_gus);   float* gus   = (float*)p;
    cudaGetSymbolAddress(&p, g_acts);  float* acts  = (float*)p;
    cudaGetSymbolAddress(&p, g_gur);   float* gur   = (float*)p;
    cudaGetSymbolAddress(&p, g_actr);  float* actr  = (float*)p;
    cudaGetSymbolAddress(&p, g_ptok);  const int* tok = (const int*)p;
    cudaGetSymbolAddress(&p, g_pgp);   const int* gp  = (const int*)p;
    cudaGetSymbolAddress(&p, g_pscl);  const float* psc = (const float*)p;
    cudaGetSymbolAddress(&p, g_cnt);   const int* cnt = (const int*)p;

    cudaFuncSetAttribute(gemm_tf32, cudaFuncAttributeMaxDynamicSharedMemorySize, DYN_SMEM);

    int writeScores = (out_size >= T_DIM * H_DIM + E_DIM * T_DIM) ? 1 : 0;

    zero_cnt_kernel<<<1, 32>>>();
    router_kernel<<<T_DIM / 8, 256>>>(x, rw, out, writeScores);

    // prepass: round + k-permute NT operands (x, shared weights)
    round_perm_copy<<<2048, 256>>>((const float4*)x,  (float4*)rx,
                                   (long)T_DIM * H_DIM / 8);
    round_perm_copy<<<2048, 256>>>((const float4*)sg, (float4*)wsgu,
                                   (long)I_DIM * H_DIM / 8);
    round_perm_copy<<<2048, 256>>>((const float4*)su,
                                   (float4*)(wsgu + (size_t)I_DIM * H_DIM),
                                   (long)I_DIM * H_DIM / 8);
    round_perm_copy<<<2048, 256>>>((const float4*)sd, (float4*)rsd,
                                   (long)H_DIM * I_DIM / 8);

    // GEMM1: gu_s[T, 5760] = rx @ wsgu^T            (NT)
    gemm_tf32<<<dim3((GU_DIM + BN - 1) / BN, T_DIM / BM, 1), 256, DYN_SMEM>>>(
        rx, wsgu, gus, T_DIM, GU_DIM, H_DIM, H_DIM, GU_DIM, 0, 0,
        nullptr, nullptr, nullptr, nullptr, 0);

    act_perm_kernel<<<2048, 256>>>(gus, acts, T_DIM);

    // GEMM2: out[T, H] = act_s @ rsd^T              (NT)
    gemm_tf32<<<dim3(H_DIM / BN, T_DIM / BM, 1), 256, DYN_SMEM>>>(
        acts, rsd, out, T_DIM, H_DIM, I_DIM, I_DIM, H_DIM, 0, 0,
        nullptr, nullptr, nullptr, nullptr, 0);

    // GEMM3: gu_r[gp, 5760] = score * (rx[tok] @ gup_e)   (NN, raw weights)
    gemm_tf32<<<dim3((GU_DIM + BN - 1) / BN, T_DIM / BM, E_DIM), 256, DYN_SMEM>>>(
        rx, gup, gur, T_DIM, GU_DIM, H_DIM, GU_DIM, GU_DIM, 1, 1 | 2 | 4,
        tok, gp, psc, cnt, (size_t)H_DIM * GU_DIM);

    act_perm_kernel<<<2048, 256>>>(gur, actr, 2 * T_DIM);

    // GEMM4: out[tok, H] += act_r[gp] @ dwn_e       (NN, raw weights)
    gemm_tf32<<<dim3(H_DIM / BN, T_DIM / BM, E_DIM), 256, DYN_SMEM>>>(
        actr, dwn, out, T_DIM, H_DIM, I_DIM, H_DIM, H_DIM, 1, 1 | 2 | 8,
        gp, tok, nullptr, cnt, (size_t)I_DIM * H_DIM);
}